// round 8
// baseline (speedup 1.0000x reference)
#include <cuda_runtime.h>
#include <cuda_bf16.h>

// Problem constants
#define B    4
#define N    512
#define M    512
#define LDIM 512
#define RDIM 512
#define AGG  256
#define ROWS (B * N)          // 2048 rows for both projections

// ---------------------------------------------------------------------------
// Scratch (no cudaMalloc allowed): projected activations
// ---------------------------------------------------------------------------
__device__ float g_dlin[B * N * AGG];   // [2048][256]
__device__ float g_clin[B * M * AGG];   // [2048][256]

__device__ __forceinline__ float tanh_approx(float x) {
    float y;
    asm("tanh.approx.f32 %0, %1;" : "=f"(y) : "f"(x));
    return y;
}

// ---------------------------------------------------------------------------
// Projection GEMM: C[r][a] = sum_k X[r][k] * W[k][a] + bias[a]
// X: [2048][512], W: [512][256]. blockIdx.z selects (data,Wl,bl) / (crit,Wr,br).
// BM=64, BN=64, BK=16, 256 threads, 4x4 per thread.
// ---------------------------------------------------------------------------
#define BM 64
#define BN 64
#define BK 16

__global__ __launch_bounds__(256)
void proj_kernel(const float* __restrict__ data, const float* __restrict__ crit,
                 const float* __restrict__ Wl, const float* __restrict__ bl,
                 const float* __restrict__ Wr, const float* __restrict__ br) {
    __shared__ __align__(16) float Xs[BK][68];  // transposed: Xs[k][m], pitch 68 (16B-aligned rows)
    __shared__ __align__(16) float Ws[BK][68];  // Ws[k][n]

    const float* X;
    const float* W;
    const float* bias;
    float* C;
    if (blockIdx.z == 0) { X = data; W = Wl; bias = bl; C = g_dlin; }
    else                 { X = crit; W = Wr; bias = br; C = g_clin; }

    const int tid = threadIdx.x;
    const int m0 = blockIdx.x * BM;     // row tile
    const int n0 = blockIdx.y * BN;     // col tile

    // load mapping
    const int xRow = tid >> 2;            // 0..63
    const int xCol = (tid & 3) << 2;      // 0,4,8,12
    const int wRow = tid >> 4;            // 0..15
    const int wCol = (tid & 15) << 2;     // 0..60

    // compute mapping: 16x16 threads, 4x4 micro-tile
    const int tm = (tid & 15) << 2;       // row offset 0..60
    const int tn = (tid >> 4) << 2;       // col offset 0..60

    float acc[4][4];
#pragma unroll
    for (int i = 0; i < 4; i++)
#pragma unroll
        for (int j = 0; j < 4; j++) acc[i][j] = 0.0f;

    for (int k0 = 0; k0 < LDIM; k0 += BK) {
        float4 xv = *(const float4*)&X[(m0 + xRow) * LDIM + k0 + xCol];
        Xs[xCol + 0][xRow] = xv.x;
        Xs[xCol + 1][xRow] = xv.y;
        Xs[xCol + 2][xRow] = xv.z;
        Xs[xCol + 3][xRow] = xv.w;
        float4 wv = *(const float4*)&W[(k0 + wRow) * AGG + n0 + wCol];
        *(float4*)&Ws[wRow][wCol] = wv;
        __syncthreads();

#pragma unroll
        for (int k = 0; k < BK; k++) {
            float4 av = *(const float4*)&Xs[k][tm];
            float4 bv = *(const float4*)&Ws[k][tn];
            float a[4] = {av.x, av.y, av.z, av.w};
            float b[4] = {bv.x, bv.y, bv.z, bv.w};
#pragma unroll
            for (int i = 0; i < 4; i++)
#pragma unroll
                for (int j = 0; j < 4; j++)
                    acc[i][j] = fmaf(a[i], b[j], acc[i][j]);
        }
        __syncthreads();
    }

    // epilogue: add bias, store
    float4 bv = *(const float4*)&bias[n0 + tn];
    float bb[4] = {bv.x, bv.y, bv.z, bv.w};
#pragma unroll
    for (int i = 0; i < 4; i++) {
        float4 o;
        o.x = acc[i][0] + bb[0];
        o.y = acc[i][1] + bb[1];
        o.z = acc[i][2] + bb[2];
        o.w = acc[i][3] + bb[3];
        *(float4*)&C[(m0 + tm + i) * AGG + n0 + tn] = o;
    }
}

// ---------------------------------------------------------------------------
// Distance kernel: out[b][n][m] = sum_a tanh(dlin[b][n][a] + clin[b][m][a]) * agg[a]
// Tile: 32 n x 32 m, A chunked by 128. Smem stored transposed [a][row] with
// pitch 33 -> conflict-free transposing STS (a+r covers all banks) and
// broadcast-only LDS in the inner loop. 2x2 per thread, 256 threads.
// ---------------------------------------------------------------------------
#define TN  32
#define TM  32
#define ACH 128

__global__ __launch_bounds__(256)
void dist_kernel(const float* __restrict__ agg, float* __restrict__ out) {
    __shared__ float dl[ACH][TN + 1];   // pitch 33
    __shared__ float cl[ACH][TM + 1];
    __shared__ float ag[ACH];

    const int b  = blockIdx.z;
    const int n0 = blockIdx.y * TN;
    const int m0 = blockIdx.x * TM;
    const int tid = threadIdx.x;

    const int tx = tid & 15;   // m-dir
    const int ty = tid >> 4;   // n-dir

    const int ldRow = tid >> 3;           // 0..31
    const int ldA   = (tid & 7) << 2;     // 0,4,...,28

    float acc00 = 0.f, acc01 = 0.f, acc10 = 0.f, acc11 = 0.f;

    const long dBase = ((long)(b * N + n0 + ldRow)) * AGG;
    const long cBase = ((long)(b * M + m0 + ldRow)) * AGG;

    for (int a0 = 0; a0 < AGG; a0 += ACH) {
        // load 32 rows x 128 a of each activation, transposed into smem
#pragma unroll
        for (int i = 0; i < 4; i++) {
            int a = ldA + (i << 5);
            float4 v = *(const float4*)&g_dlin[dBase + a0 + a];
            dl[a + 0][ldRow] = v.x;
            dl[a + 1][ldRow] = v.y;
            dl[a + 2][ldRow] = v.z;
            dl[a + 3][ldRow] = v.w;
            float4 w = *(const float4*)&g_clin[cBase + a0 + a];
            cl[a + 0][ldRow] = w.x;
            cl[a + 1][ldRow] = w.y;
            cl[a + 2][ldRow] = w.z;
            cl[a + 3][ldRow] = w.w;
        }
        if (tid < ACH) ag[tid] = agg[a0 + tid];
        __syncthreads();

#pragma unroll 4
        for (int a = 0; a < ACH; a++) {
            float ga = ag[a];
            float d0 = dl[a][2 * ty];
            float d1 = dl[a][2 * ty + 1];
            float c0 = cl[a][2 * tx];
            float c1 = cl[a][2 * tx + 1];
            acc00 = fmaf(tanh_approx(d0 + c0), ga, acc00);
            acc01 = fmaf(tanh_approx(d0 + c1), ga, acc01);
            acc10 = fmaf(tanh_approx(d1 + c0), ga, acc10);
            acc11 = fmaf(tanh_approx(d1 + c1), ga, acc11);
        }
        __syncthreads();
    }

    const int n = n0 + 2 * ty;
    const int m = m0 + 2 * tx;
    float2 r0 = make_float2(acc00, acc01);
    float2 r1 = make_float2(acc10, acc11);
    *(float2*)&out[((long)(b * N + n)     ) * M + m] = r0;
    *(float2*)&out[((long)(b * N + n + 1)) * M + m] = r1;
}

// ---------------------------------------------------------------------------
// kernel_launch
// Inputs (metadata order): data, crit, Wl, bl, Wr, br, agg
// ---------------------------------------------------------------------------
extern "C" void kernel_launch(void* const* d_in, const int* in_sizes, int n_in,
                              void* d_out, int out_size) {
    const float* data = (const float*)d_in[0];
    const float* crit = (const float*)d_in[1];
    const float* Wl   = (const float*)d_in[2];
    const float* bl   = (const float*)d_in[3];
    const float* Wr   = (const float*)d_in[4];
    const float* br   = (const float*)d_in[5];
    const float* agg  = (const float*)d_in[6];
    float* out = (float*)d_out;

    dim3 gProj(ROWS / BM, AGG / BN, 2);       // (32, 4, 2)
    proj_kernel<<<gProj, 256>>>(data, crit, Wl, bl, Wr, br);

    dim3 gDist(M / TM, N / TN, B);            // (16, 16, 4)
    dist_kernel<<<gDist, 256>>>(agg, out);
}

// round 9
// speedup vs baseline: 1.0025x; 1.0025x over previous
#include <cuda_runtime.h>
#include <cuda_bf16.h>

// Problem constants
#define B    4
#define N    512
#define M    512
#define LDIM 512
#define RDIM 512
#define AGG  256
#define ROWS (B * N)          // 2048 rows for both projections

// ---------------------------------------------------------------------------
// Scratch (no cudaMalloc allowed): projected activations
// ---------------------------------------------------------------------------
__device__ float g_dlin[B * N * AGG];   // [2048][256]
__device__ float g_clin[B * M * AGG];   // [2048][256]

__device__ __forceinline__ float tanh_approx(float x) {
    float y;
    asm("tanh.approx.f32 %0, %1;" : "=f"(y) : "f"(x));
    return y;
}

// ---------------------------------------------------------------------------
// Projection GEMM: C[r][a] = sum_k X[r][k] * W[k][a] + bias[a]
// X: [2048][512], W: [512][256]. blockIdx.z selects (data,Wl,bl) / (crit,Wr,br).
// BM=64, BN=64, BK=16, 256 threads, 4x4 per thread.
// ---------------------------------------------------------------------------
#define BM 64
#define BN 64
#define BK 16

__global__ __launch_bounds__(256)
void proj_kernel(const float* __restrict__ data, const float* __restrict__ crit,
                 const float* __restrict__ Wl, const float* __restrict__ bl,
                 const float* __restrict__ Wr, const float* __restrict__ br) {
    __shared__ __align__(16) float Xs[BK][68];  // transposed: Xs[k][m], pitch 68 (16B-aligned rows)
    __shared__ __align__(16) float Ws[BK][68];  // Ws[k][n]

    const float* X;
    const float* W;
    const float* bias;
    float* C;
    if (blockIdx.z == 0) { X = data; W = Wl; bias = bl; C = g_dlin; }
    else                 { X = crit; W = Wr; bias = br; C = g_clin; }

    const int tid = threadIdx.x;
    const int m0 = blockIdx.x * BM;     // row tile
    const int n0 = blockIdx.y * BN;     // col tile

    // load mapping
    const int xRow = tid >> 2;            // 0..63
    const int xCol = (tid & 3) << 2;      // 0,4,8,12
    const int wRow = tid >> 4;            // 0..15
    const int wCol = (tid & 15) << 2;     // 0..60

    // compute mapping: 16x16 threads, 4x4 micro-tile
    const int tm = (tid & 15) << 2;       // row offset 0..60
    const int tn = (tid >> 4) << 2;       // col offset 0..60

    float acc[4][4];
#pragma unroll
    for (int i = 0; i < 4; i++)
#pragma unroll
        for (int j = 0; j < 4; j++) acc[i][j] = 0.0f;

    for (int k0 = 0; k0 < LDIM; k0 += BK) {
        float4 xv = *(const float4*)&X[(m0 + xRow) * LDIM + k0 + xCol];
        Xs[xCol + 0][xRow] = xv.x;
        Xs[xCol + 1][xRow] = xv.y;
        Xs[xCol + 2][xRow] = xv.z;
        Xs[xCol + 3][xRow] = xv.w;
        float4 wv = *(const float4*)&W[(k0 + wRow) * AGG + n0 + wCol];
        *(float4*)&Ws[wRow][wCol] = wv;
        __syncthreads();

#pragma unroll
        for (int k = 0; k < BK; k++) {
            float4 av = *(const float4*)&Xs[k][tm];
            float4 bv = *(const float4*)&Ws[k][tn];
            float a[4] = {av.x, av.y, av.z, av.w};
            float b[4] = {bv.x, bv.y, bv.z, bv.w};
#pragma unroll
            for (int i = 0; i < 4; i++)
#pragma unroll
                for (int j = 0; j < 4; j++)
                    acc[i][j] = fmaf(a[i], b[j], acc[i][j]);
        }
        __syncthreads();
    }

    // epilogue: add bias, store
    float4 bv = *(const float4*)&bias[n0 + tn];
    float bb[4] = {bv.x, bv.y, bv.z, bv.w};
#pragma unroll
    for (int i = 0; i < 4; i++) {
        float4 o;
        o.x = acc[i][0] + bb[0];
        o.y = acc[i][1] + bb[1];
        o.z = acc[i][2] + bb[2];
        o.w = acc[i][3] + bb[3];
        *(float4*)&C[(m0 + tm + i) * AGG + n0 + tn] = o;
    }
}

// ---------------------------------------------------------------------------
// Distance kernel: out[b][n][m] = sum_a tanh(dlin[b][n][a] + clin[b][m][a]) * agg[a]
// Tile: 32 n x 32 m, A chunked by 128. Smem stored transposed [a][row] with
// pitch 33 -> conflict-free transposing STS (a+r covers all banks) and
// broadcast-only LDS in the inner loop. 2x2 per thread, 256 threads.
// ---------------------------------------------------------------------------
#define TN  32
#define TM  32
#define ACH 128

__global__ __launch_bounds__(256)
void dist_kernel(const float* __restrict__ agg, float* __restrict__ out) {
    __shared__ float dl[ACH][TN + 1];   // pitch 33
    __shared__ float cl[ACH][TM + 1];
    __shared__ float ag[ACH];

    const int b  = blockIdx.z;
    const int n0 = blockIdx.y * TN;
    const int m0 = blockIdx.x * TM;
    const int tid = threadIdx.x;

    const int tx = tid & 15;   // m-dir
    const int ty = tid >> 4;   // n-dir

    const int ldRow = tid >> 3;           // 0..31
    const int ldA   = (tid & 7) << 2;     // 0,4,...,28

    float acc00 = 0.f, acc01 = 0.f, acc10 = 0.f, acc11 = 0.f;

    const long dBase = ((long)(b * N + n0 + ldRow)) * AGG;
    const long cBase = ((long)(b * M + m0 + ldRow)) * AGG;

    for (int a0 = 0; a0 < AGG; a0 += ACH) {
        // load 32 rows x 128 a of each activation, transposed into smem
#pragma unroll
        for (int i = 0; i < 4; i++) {
            int a = ldA + (i << 5);
            float4 v = *(const float4*)&g_dlin[dBase + a0 + a];
            dl[a + 0][ldRow] = v.x;
            dl[a + 1][ldRow] = v.y;
            dl[a + 2][ldRow] = v.z;
            dl[a + 3][ldRow] = v.w;
            float4 w = *(const float4*)&g_clin[cBase + a0 + a];
            cl[a + 0][ldRow] = w.x;
            cl[a + 1][ldRow] = w.y;
            cl[a + 2][ldRow] = w.z;
            cl[a + 3][ldRow] = w.w;
        }
        if (tid < ACH) ag[tid] = agg[a0 + tid];
        __syncthreads();

#pragma unroll 4
        for (int a = 0; a < ACH; a++) {
            float ga = ag[a];
            float d0 = dl[a][2 * ty];
            float d1 = dl[a][2 * ty + 1];
            float c0 = cl[a][2 * tx];
            float c1 = cl[a][2 * tx + 1];
            acc00 = fmaf(tanh_approx(d0 + c0), ga, acc00);
            acc01 = fmaf(tanh_approx(d0 + c1), ga, acc01);
            acc10 = fmaf(tanh_approx(d1 + c0), ga, acc10);
            acc11 = fmaf(tanh_approx(d1 + c1), ga, acc11);
        }
        __syncthreads();
    }

    const int n = n0 + 2 * ty;
    const int m = m0 + 2 * tx;
    float2 r0 = make_float2(acc00, acc01);
    float2 r1 = make_float2(acc10, acc11);
    *(float2*)&out[((long)(b * N + n)     ) * M + m] = r0;
    *(float2*)&out[((long)(b * N + n + 1)) * M + m] = r1;
}

// ---------------------------------------------------------------------------
// kernel_launch
// Inputs (metadata order): data, crit, Wl, bl, Wr, br, agg
// ---------------------------------------------------------------------------
extern "C" void kernel_launch(void* const* d_in, const int* in_sizes, int n_in,
                              void* d_out, int out_size) {
    const float* data = (const float*)d_in[0];
    const float* crit = (const float*)d_in[1];
    const float* Wl   = (const float*)d_in[2];
    const float* bl   = (const float*)d_in[3];
    const float* Wr   = (const float*)d_in[4];
    const float* br   = (const float*)d_in[5];
    const float* agg  = (const float*)d_in[6];
    float* out = (float*)d_out;

    dim3 gProj(ROWS / BM, AGG / BN, 2);       // (32, 4, 2)
    proj_kernel<<<gProj, 256>>>(data, crit, Wl, bl, Wr, br);

    dim3 gDist(M / TM, N / TN, B);            // (16, 16, 4)
    dist_kernel<<<gDist, 256>>>(agg, out);
}

// round 10
// speedup vs baseline: 1.0044x; 1.0019x over previous
#include <cuda_runtime.h>
#include <cuda_bf16.h>

// Problem constants
#define B    4
#define N    512
#define M    512
#define LDIM 512
#define RDIM 512
#define AGG  256
#define ROWS (B * N)          // 2048 rows for both projections

// ---------------------------------------------------------------------------
// Scratch (no cudaMalloc allowed): projected activations
// ---------------------------------------------------------------------------
__device__ float g_dlin[B * N * AGG];   // [2048][256]
__device__ float g_clin[B * M * AGG];   // [2048][256]

__device__ __forceinline__ float tanh_approx(float x) {
    float y;
    asm("tanh.approx.f32 %0, %1;" : "=f"(y) : "f"(x));
    return y;
}

// ---------------------------------------------------------------------------
// Projection GEMM: C[r][a] = sum_k X[r][k] * W[k][a] + bias[a]
// X: [2048][512], W: [512][256]. blockIdx.z selects (data,Wl,bl) / (crit,Wr,br).
// BM=64, BN=64, BK=16, 256 threads, 4x4 per thread.
// ---------------------------------------------------------------------------
#define BM 64
#define BN 64
#define BK 16

__global__ __launch_bounds__(256)
void proj_kernel(const float* __restrict__ data, const float* __restrict__ crit,
                 const float* __restrict__ Wl, const float* __restrict__ bl,
                 const float* __restrict__ Wr, const float* __restrict__ br) {
    __shared__ __align__(16) float Xs[BK][68];  // transposed: Xs[k][m], pitch 68 (16B-aligned rows)
    __shared__ __align__(16) float Ws[BK][68];  // Ws[k][n]

    const float* X;
    const float* W;
    const float* bias;
    float* C;
    if (blockIdx.z == 0) { X = data; W = Wl; bias = bl; C = g_dlin; }
    else                 { X = crit; W = Wr; bias = br; C = g_clin; }

    const int tid = threadIdx.x;
    const int m0 = blockIdx.x * BM;     // row tile
    const int n0 = blockIdx.y * BN;     // col tile

    // load mapping
    const int xRow = tid >> 2;            // 0..63
    const int xCol = (tid & 3) << 2;      // 0,4,8,12
    const int wRow = tid >> 4;            // 0..15
    const int wCol = (tid & 15) << 2;     // 0..60

    // compute mapping: 16x16 threads, 4x4 micro-tile
    const int tm = (tid & 15) << 2;       // row offset 0..60
    const int tn = (tid >> 4) << 2;       // col offset 0..60

    float acc[4][4];
#pragma unroll
    for (int i = 0; i < 4; i++)
#pragma unroll
        for (int j = 0; j < 4; j++) acc[i][j] = 0.0f;

    for (int k0 = 0; k0 < LDIM; k0 += BK) {
        float4 xv = *(const float4*)&X[(m0 + xRow) * LDIM + k0 + xCol];
        Xs[xCol + 0][xRow] = xv.x;
        Xs[xCol + 1][xRow] = xv.y;
        Xs[xCol + 2][xRow] = xv.z;
        Xs[xCol + 3][xRow] = xv.w;
        float4 wv = *(const float4*)&W[(k0 + wRow) * AGG + n0 + wCol];
        *(float4*)&Ws[wRow][wCol] = wv;
        __syncthreads();

#pragma unroll
        for (int k = 0; k < BK; k++) {
            float4 av = *(const float4*)&Xs[k][tm];
            float4 bv = *(const float4*)&Ws[k][tn];
            float a[4] = {av.x, av.y, av.z, av.w};
            float b[4] = {bv.x, bv.y, bv.z, bv.w};
#pragma unroll
            for (int i = 0; i < 4; i++)
#pragma unroll
                for (int j = 0; j < 4; j++)
                    acc[i][j] = fmaf(a[i], b[j], acc[i][j]);
        }
        __syncthreads();
    }

    // epilogue: add bias, store
    float4 bv = *(const float4*)&bias[n0 + tn];
    float bb[4] = {bv.x, bv.y, bv.z, bv.w};
#pragma unroll
    for (int i = 0; i < 4; i++) {
        float4 o;
        o.x = acc[i][0] + bb[0];
        o.y = acc[i][1] + bb[1];
        o.z = acc[i][2] + bb[2];
        o.w = acc[i][3] + bb[3];
        *(float4*)&C[(m0 + tm + i) * AGG + n0 + tn] = o;
    }
}

// ---------------------------------------------------------------------------
// Distance kernel: out[b][n][m] = sum_a tanh(dlin[b][n][a] + clin[b][m][a]) * agg[a]
// Tile: 32 n x 32 m, A chunked by 128. Smem stored transposed [a][row] with
// pitch 33 -> conflict-free transposing STS (a+r covers all banks) and
// broadcast-only LDS in the inner loop. 2x2 per thread, 256 threads.
// ---------------------------------------------------------------------------
#define TN  32
#define TM  32
#define ACH 128

__global__ __launch_bounds__(256)
void dist_kernel(const float* __restrict__ agg, float* __restrict__ out) {
    __shared__ float dl[ACH][TN + 1];   // pitch 33
    __shared__ float cl[ACH][TM + 1];
    __shared__ float ag[ACH];

    const int b  = blockIdx.z;
    const int n0 = blockIdx.y * TN;
    const int m0 = blockIdx.x * TM;
    const int tid = threadIdx.x;

    const int tx = tid & 15;   // m-dir
    const int ty = tid >> 4;   // n-dir

    const int ldRow = tid >> 3;           // 0..31
    const int ldA   = (tid & 7) << 2;     // 0,4,...,28

    float acc00 = 0.f, acc01 = 0.f, acc10 = 0.f, acc11 = 0.f;

    const long dBase = ((long)(b * N + n0 + ldRow)) * AGG;
    const long cBase = ((long)(b * M + m0 + ldRow)) * AGG;

    for (int a0 = 0; a0 < AGG; a0 += ACH) {
        // load 32 rows x 128 a of each activation, transposed into smem
#pragma unroll
        for (int i = 0; i < 4; i++) {
            int a = ldA + (i << 5);
            float4 v = *(const float4*)&g_dlin[dBase + a0 + a];
            dl[a + 0][ldRow] = v.x;
            dl[a + 1][ldRow] = v.y;
            dl[a + 2][ldRow] = v.z;
            dl[a + 3][ldRow] = v.w;
            float4 w = *(const float4*)&g_clin[cBase + a0 + a];
            cl[a + 0][ldRow] = w.x;
            cl[a + 1][ldRow] = w.y;
            cl[a + 2][ldRow] = w.z;
            cl[a + 3][ldRow] = w.w;
        }
        if (tid < ACH) ag[tid] = agg[a0 + tid];
        __syncthreads();

#pragma unroll 4
        for (int a = 0; a < ACH; a++) {
            float ga = ag[a];
            float d0 = dl[a][2 * ty];
            float d1 = dl[a][2 * ty + 1];
            float c0 = cl[a][2 * tx];
            float c1 = cl[a][2 * tx + 1];
            acc00 = fmaf(tanh_approx(d0 + c0), ga, acc00);
            acc01 = fmaf(tanh_approx(d0 + c1), ga, acc01);
            acc10 = fmaf(tanh_approx(d1 + c0), ga, acc10);
            acc11 = fmaf(tanh_approx(d1 + c1), ga, acc11);
        }
        __syncthreads();
    }

    const int n = n0 + 2 * ty;
    const int m = m0 + 2 * tx;
    float2 r0 = make_float2(acc00, acc01);
    float2 r1 = make_float2(acc10, acc11);
    *(float2*)&out[((long)(b * N + n)     ) * M + m] = r0;
    *(float2*)&out[((long)(b * N + n + 1)) * M + m] = r1;
}

// ---------------------------------------------------------------------------
// kernel_launch
// Inputs (metadata order): data, crit, Wl, bl, Wr, br, agg
// ---------------------------------------------------------------------------
extern "C" void kernel_launch(void* const* d_in, const int* in_sizes, int n_in,
                              void* d_out, int out_size) {
    const float* data = (const float*)d_in[0];
    const float* crit = (const float*)d_in[1];
    const float* Wl   = (const float*)d_in[2];
    const float* bl   = (const float*)d_in[3];
    const float* Wr   = (const float*)d_in[4];
    const float* br   = (const float*)d_in[5];
    const float* agg  = (const float*)d_in[6];
    float* out = (float*)d_out;

    dim3 gProj(ROWS / BM, AGG / BN, 2);       // (32, 4, 2)
    proj_kernel<<<gProj, 256>>>(data, crit, Wl, bl, Wr, br);

    dim3 gDist(M / TM, N / TN, B);            // (16, 16, 4)
    dist_kernel<<<gDist, 256>>>(agg, out);
}